// round 4
// baseline (speedup 1.0000x reference)
#include <cuda_runtime.h>

#define N_NODES 100000
#define N_EDGES 1600000
#define HID 64
#define EDIM 32
#define MAXDEG 64
#define N_LAYERS 3
#define BN_EPS 1e-5f

// ---------------- scratch (static device globals; no allocation) ----------------
__device__ float g_agg[(size_t)N_NODES * HID];   // 25.6 MB
__device__ float g_tmp[(size_t)N_NODES * HID];   // 25.6 MB (pre-BN activations)
__device__ float g_bufA[(size_t)N_NODES * HID];  // ping
__device__ float g_bufB[(size_t)N_NODES * HID];  // pong
__device__ float g_stats[N_LAYERS * 2 * HID];    // per-layer [sum(64), sumsq(64)]
__device__ int   g_deg[N_NODES];
__device__ int   g_src[(size_t)N_NODES * MAXDEG]; // 25.6 MB
__device__ int   g_eid[(size_t)N_NODES * MAXDEG]; // 25.6 MB

__device__ __forceinline__ const float* sel_x(const float* xext, int sel) {
    return sel == 0 ? xext : (sel == 1 ? (const float*)g_bufA : (const float*)g_bufB);
}

// ---------------- init: zero degree counters + BN stat accumulators ----------------
__global__ void zero_kernel() {
    int i = blockIdx.x * blockDim.x + threadIdx.x;
    if (i < N_NODES) g_deg[i] = 0;
    if (i < N_LAYERS * 2 * HID) g_stats[i] = 0.0f;
}

// ---------------- padded-CSR build (once per launch; edge_index constant across layers) ----
__global__ void build_csr_kernel(const int* __restrict__ ei) {
    int e = blockIdx.x * blockDim.x + threadIdx.x;
    if (e >= N_EDGES) return;
    int src = ei[e];            // edge_index[0] = message source
    int dst = ei[N_EDGES + e];  // edge_index[1] = aggregation target
    int slot = atomicAdd(&g_deg[dst], 1);
    if (slot < MAXDEG) {
        g_src[(size_t)dst * MAXDEG + slot] = src;
        g_eid[(size_t)dst * MAXDEG + slot] = e;
    }
}

// ---------------- edge aggregation: warp per node, We register-resident ----------------
// agg[n] = sum over incoming edges e of relu( x[src_e] + edge_attr[e] @ We + be )
__global__ void __launch_bounds__(256) agg_kernel(
    const float* __restrict__ xext, int xsel,
    const float* __restrict__ attr,
    const float* __restrict__ We,  // [32][64] layer slice
    const float* __restrict__ be)  // [64]
{
    int warp = (blockIdx.x * 256 + threadIdx.x) >> 5;
    int lane = threadIdx.x & 31;
    if (warp >= N_NODES) return;

    const float* x = sel_x(xext, xsel);
    const float2* x2 = (const float2*)x;

    // lane owns output features (2*lane, 2*lane+1); weights in registers: 64 regs
    float2 w[EDIM];
    const float2* We2 = (const float2*)We;
#pragma unroll
    for (int k = 0; k < EDIM; k++) w[k] = We2[k * (HID / 2) + lane];
    float2 bias = ((const float2*)be)[lane];

    int d = g_deg[warp];
    if (d > MAXDEG) d = MAXDEG;

    float accx = 0.0f, accy = 0.0f;
    const int* srcp = g_src + (size_t)warp * MAXDEG;
    const int* eidp = g_eid + (size_t)warp * MAXDEG;

    for (int base = 0; base < d; base += 32) {
        int cnt = d - base;
        if (cnt > 32) cnt = 32;
        int sl = 0, el = 0;
        if (lane < cnt) { sl = srcp[base + lane]; el = eidp[base + lane]; }
        for (int j = 0; j < cnt; j++) {
            int src = __shfl_sync(0xffffffffu, sl, j);
            int eid = __shfl_sync(0xffffffffu, el, j);
            const float4* ap = (const float4*)(attr + (size_t)eid * EDIM);
            // two accumulator chains to break the FFMA dependency chain
            float e0x = bias.x, e0y = bias.y;
            float e1x = 0.0f,  e1y = 0.0f;
#pragma unroll
            for (int q = 0; q < 8; q += 2) {
                float4 a = __ldg(ap + q);       // broadcast load (same addr all lanes)
                e0x += a.x * w[4*q+0].x; e0y += a.x * w[4*q+0].y;
                e0x += a.y * w[4*q+1].x; e0y += a.y * w[4*q+1].y;
                e0x += a.z * w[4*q+2].x; e0y += a.z * w[4*q+2].y;
                e0x += a.w * w[4*q+3].x; e0y += a.w * w[4*q+3].y;
                float4 b = __ldg(ap + q + 1);
                e1x += b.x * w[4*q+4].x; e1y += b.x * w[4*q+4].y;
                e1x += b.y * w[4*q+5].x; e1y += b.y * w[4*q+5].y;
                e1x += b.z * w[4*q+6].x; e1y += b.z * w[4*q+6].y;
                e1x += b.w * w[4*q+7].x; e1y += b.w * w[4*q+7].y;
            }
            float2 xs = x2[(size_t)src * (HID / 2) + lane];  // coalesced gather
            accx += fmaxf(xs.x + e0x + e1x, 0.0f);
            accy += fmaxf(xs.y + e0y + e1y, 0.0f);
        }
    }
    float2 o; o.x = accx; o.y = accy;
    ((float2*)g_agg)[(size_t)warp * (HID / 2) + lane] = o;
}

// ---------------- node MLP: t = relu((x+agg)@W1+b1)@W2+b2  (64 rows per block) ------------
__global__ void __launch_bounds__(64) mlp_kernel(
    const float* __restrict__ xext, int xsel,
    const float* __restrict__ W1, const float* __restrict__ b1,
    const float* __restrict__ W2, const float* __restrict__ b2)
{
    __shared__ float sh[64 * 65];     // padded row tile (bank-conflict-free column reads)
    __shared__ float4 sW[64 * 16];    // one weight matrix at a time
    const float* x = sel_x(xext, xsel);
    int tid = threadIdx.x;
    int rowbase = blockIdx.x * 64;

    // stage h = x + agg (coalesced)
    for (int i = tid; i < 64 * 64; i += 64) {
        int r = i >> 6, c = i & 63;
        float v = 0.0f;
        if (rowbase + r < N_NODES) {
            size_t g = (size_t)(rowbase + r) * HID + c;
            v = x[g] + g_agg[g];
        }
        sh[r * 65 + c] = v;
    }
    for (int i = tid; i < 1024; i += 64) sW[i] = ((const float4*)W1)[i];
    __syncthreads();

    float4 acc[16];
#pragma unroll
    for (int j = 0; j < 16; j++) acc[j] = __ldg((const float4*)b1 + j);
    for (int k = 0; k < 64; k++) {
        float hk = sh[tid * 65 + k];
#pragma unroll
        for (int j = 0; j < 16; j++) {
            float4 wv = sW[k * 16 + j];   // uniform-address broadcast LDS
            acc[j].x += hk * wv.x; acc[j].y += hk * wv.y;
            acc[j].z += hk * wv.z; acc[j].w += hk * wv.w;
        }
    }
    __syncthreads();
    // relu -> new h in shared
#pragma unroll
    for (int j = 0; j < 16; j++) {
        sh[tid * 65 + 4*j + 0] = fmaxf(acc[j].x, 0.0f);
        sh[tid * 65 + 4*j + 1] = fmaxf(acc[j].y, 0.0f);
        sh[tid * 65 + 4*j + 2] = fmaxf(acc[j].z, 0.0f);
        sh[tid * 65 + 4*j + 3] = fmaxf(acc[j].w, 0.0f);
    }
    for (int i = tid; i < 1024; i += 64) sW[i] = ((const float4*)W2)[i];
    __syncthreads();

#pragma unroll
    for (int j = 0; j < 16; j++) acc[j] = __ldg((const float4*)b2 + j);
    for (int k = 0; k < 64; k++) {
        float hk = sh[tid * 65 + k];
#pragma unroll
        for (int j = 0; j < 16; j++) {
            float4 wv = sW[k * 16 + j];
            acc[j].x += hk * wv.x; acc[j].y += hk * wv.y;
            acc[j].z += hk * wv.z; acc[j].w += hk * wv.w;
        }
    }
    __syncthreads();
#pragma unroll
    for (int j = 0; j < 16; j++) {
        sh[tid * 65 + 4*j + 0] = acc[j].x;
        sh[tid * 65 + 4*j + 1] = acc[j].y;
        sh[tid * 65 + 4*j + 2] = acc[j].z;
        sh[tid * 65 + 4*j + 3] = acc[j].w;
    }
    __syncthreads();
    for (int i = tid; i < 64 * 64; i += 64) {
        int r = i >> 6, c = i & 63;
        if (rowbase + r < N_NODES)
            g_tmp[(size_t)(rowbase + r) * HID + c] = sh[r * 65 + c];
    }
}

// ---------------- BN statistics: per-feature sum and sum-of-squares over g_tmp -------------
__global__ void __launch_bounds__(256) stats_kernel(int layer) {
    int f = threadIdx.x & 63;
    int rg = threadIdx.x >> 6;  // 0..3
    float s = 0.0f, s2 = 0.0f;
    for (int r = blockIdx.x * 4 + rg; r < N_NODES; r += gridDim.x * 4) {
        float v = g_tmp[(size_t)r * HID + f];
        s += v; s2 += v * v;
    }
    __shared__ float sh[512];
    sh[threadIdx.x] = s;
    sh[256 + threadIdx.x] = s2;
    __syncthreads();
    if (threadIdx.x < 64) {
        float ts = sh[f] + sh[64 + f] + sh[128 + f] + sh[192 + f];
        float t2 = sh[256 + f] + sh[320 + f] + sh[384 + f] + sh[448 + f];
        atomicAdd(&g_stats[layer * 128 + f], ts);
        atomicAdd(&g_stats[layer * 128 + 64 + f], t2);
    }
}

// ---------------- BN apply + relu -> next layer's x buffer ---------------------------------
__global__ void __launch_bounds__(256) bn_kernel(
    int layer, const float* __restrict__ gamma, const float* __restrict__ beta, int outsel)
{
    size_t idx = (size_t)blockIdx.x * 256 + threadIdx.x;
    if (idx >= (size_t)N_NODES * HID) return;
    int f = (int)(idx & 63);
    const float inv = 1.0f / (float)N_NODES;
    float mean = g_stats[layer * 128 + f] * inv;
    float var  = g_stats[layer * 128 + 64 + f] * inv - mean * mean;
    float v = (g_tmp[idx] - mean) * rsqrtf(var + BN_EPS) * __ldg(gamma + f) + __ldg(beta + f);
    float* o = (outsel == 1) ? g_bufA : g_bufB;
    o[idx] = fmaxf(v, 0.0f);
}

// ---------------- output head: out = x3 @ Wout + bout --------------------------------------
__global__ void __launch_bounds__(64) out_kernel(
    const float* __restrict__ xext, int xsel,
    const float* __restrict__ Wout, const float* __restrict__ bout,
    float* __restrict__ out)
{
    __shared__ float sh[64 * 65];
    __shared__ float4 sW[64 * 16];
    const float* x = sel_x(xext, xsel);
    int tid = threadIdx.x;
    int rowbase = blockIdx.x * 64;

    for (int i = tid; i < 64 * 64; i += 64) {
        int r = i >> 6, c = i & 63;
        float v = 0.0f;
        if (rowbase + r < N_NODES) v = x[(size_t)(rowbase + r) * HID + c];
        sh[r * 65 + c] = v;
    }
    for (int i = tid; i < 1024; i += 64) sW[i] = ((const float4*)Wout)[i];
    __syncthreads();

    float4 acc[16];
#pragma unroll
    for (int j = 0; j < 16; j++) acc[j] = __ldg((const float4*)bout + j);
    for (int k = 0; k < 64; k++) {
        float hk = sh[tid * 65 + k];
#pragma unroll
        for (int j = 0; j < 16; j++) {
            float4 wv = sW[k * 16 + j];
            acc[j].x += hk * wv.x; acc[j].y += hk * wv.y;
            acc[j].z += hk * wv.z; acc[j].w += hk * wv.w;
        }
    }
    __syncthreads();
#pragma unroll
    for (int j = 0; j < 16; j++) {
        sh[tid * 65 + 4*j + 0] = acc[j].x;
        sh[tid * 65 + 4*j + 1] = acc[j].y;
        sh[tid * 65 + 4*j + 2] = acc[j].z;
        sh[tid * 65 + 4*j + 3] = acc[j].w;
    }
    __syncthreads();
    for (int i = tid; i < 64 * 64; i += 64) {
        int r = i >> 6, c = i & 63;
        if (rowbase + r < N_NODES)
            out[(size_t)(rowbase + r) * HID + c] = sh[r * 65 + c];
    }
}

// ---------------- launch --------------------------------------------------------------------
extern "C" void kernel_launch(void* const* d_in, const int* in_sizes, int n_in,
                              void* d_out, int out_size) {
    const float* x     = (const float*)d_in[0];
    const int*   ei    = (const int*)  d_in[1];
    const float* ea    = (const float*)d_in[2];
    const float* We    = (const float*)d_in[3];
    const float* be    = (const float*)d_in[4];
    const float* W1    = (const float*)d_in[5];
    const float* b1    = (const float*)d_in[6];
    const float* W2    = (const float*)d_in[7];
    const float* b2    = (const float*)d_in[8];
    const float* gamma = (const float*)d_in[9];
    const float* beta  = (const float*)d_in[10];
    const float* Wout  = (const float*)d_in[11];
    const float* bout  = (const float*)d_in[12];
    float* out = (float*)d_out;

    const int AGG_BLOCKS  = (N_NODES * 32 + 255) / 256;      // 12500
    const int GEMM_BLOCKS = (N_NODES + 63) / 64;             // 1563
    const int BN_BLOCKS   = (int)(((size_t)N_NODES * HID + 255) / 256);

    zero_kernel<<<(N_NODES + 255) / 256, 256>>>();
    build_csr_kernel<<<(N_EDGES + 255) / 256, 256>>>(ei);

    // layer 0: x = input, out -> bufA (sel 1)
    agg_kernel<<<AGG_BLOCKS, 256>>>(x, 0, ea, We + 0 * EDIM * HID, be + 0 * HID);
    mlp_kernel<<<GEMM_BLOCKS, 64>>>(x, 0, W1 + 0 * HID * HID, b1 + 0 * HID,
                                    W2 + 0 * HID * HID, b2 + 0 * HID);
    stats_kernel<<<512, 256>>>(0);
    bn_kernel<<<BN_BLOCKS, 256>>>(0, gamma + 0 * HID, beta + 0 * HID, 1);

    // layer 1: in bufA (sel 1), out -> bufB (sel 2)
    agg_kernel<<<AGG_BLOCKS, 256>>>(x, 1, ea, We + 1 * EDIM * HID, be + 1 * HID);
    mlp_kernel<<<GEMM_BLOCKS, 64>>>(x, 1, W1 + 1 * HID * HID, b1 + 1 * HID,
                                    W2 + 1 * HID * HID, b2 + 1 * HID);
    stats_kernel<<<512, 256>>>(1);
    bn_kernel<<<BN_BLOCKS, 256>>>(1, gamma + 1 * HID, beta + 1 * HID, 2);

    // layer 2: in bufB (sel 2), out -> bufA (sel 1)
    agg_kernel<<<AGG_BLOCKS, 256>>>(x, 2, ea, We + 2 * EDIM * HID, be + 2 * HID);
    mlp_kernel<<<GEMM_BLOCKS, 64>>>(x, 2, W1 + 2 * HID * HID, b1 + 2 * HID,
                                    W2 + 2 * HID * HID, b2 + 2 * HID);
    stats_kernel<<<512, 256>>>(2);
    bn_kernel<<<BN_BLOCKS, 256>>>(2, gamma + 2 * HID, beta + 2 * HID, 1);

    // output head: in bufA (sel 1)
    out_kernel<<<GEMM_BLOCKS, 64>>>(x, 1, Wout, bout, out);
}

// round 5
// speedup vs baseline: 1.6724x; 1.6724x over previous
#include <cuda_runtime.h>

#define N_NODES 100000
#define N_EDGES 1600000
#define HID 64
#define EDIM 32
#define MAXDEG 64
#define N_LAYERS 3
#define BN_EPS 1e-5f

typedef unsigned long long u64;

// ---------------- scratch (static device globals; no allocation) ----------------
__device__ float g_agg[(size_t)N_NODES * HID];
__device__ float g_tmp[(size_t)N_NODES * HID];
__device__ float g_bufA[(size_t)N_NODES * HID];
__device__ float g_bufB[(size_t)N_NODES * HID];
__device__ float g_stats[N_LAYERS * 2 * HID];
__device__ int   g_deg[N_NODES];
__device__ int   g_src[(size_t)N_NODES * MAXDEG];
__device__ int   g_slot[N_EDGES];                         // CSR slot for each edge (-1 = overflow)
__device__ float g_attr_p[(size_t)N_NODES * MAXDEG * EDIM]; // attr permuted to CSR order (819MB)

__device__ __forceinline__ const float* sel_x(const float* xext, int sel) {
    return sel == 0 ? xext : (sel == 1 ? (const float*)g_bufA : (const float*)g_bufB);
}

// ---------------- packed f32x2 helpers (FFMA2 path; PTX-only) ----------------
__device__ __forceinline__ u64 pk(float s) {
    u64 r; asm("mov.b64 %0, {%1, %1};" : "=l"(r) : "f"(s)); return r;
}
__device__ __forceinline__ void fma2(u64& d, u64 a, u64 b) {
    asm("fma.rn.f32x2 %0, %1, %2, %0;" : "+l"(d) : "l"(a), "l"(b));
}
__device__ __forceinline__ u64 add2(u64 a, u64 b) {
    u64 d; asm("add.rn.f32x2 %0, %1, %2;" : "=l"(d) : "l"(a), "l"(b)); return d;
}
__device__ __forceinline__ void unpk(u64 v, float& lo, float& hi) {
    asm("mov.b64 {%0, %1}, %2;" : "=f"(lo), "=f"(hi) : "l"(v));
}
__device__ __forceinline__ void mac4(u64& acc, float4 a, const u64* wp) {
    fma2(acc, pk(a.x), wp[0]); fma2(acc, pk(a.y), wp[1]);
    fma2(acc, pk(a.z), wp[2]); fma2(acc, pk(a.w), wp[3]);
}

// ---------------- init ----------------
__global__ void zero_kernel() {
    int i = blockIdx.x * blockDim.x + threadIdx.x;
    if (i < N_NODES) g_deg[i] = 0;
    if (i < N_LAYERS * 2 * HID) g_stats[i] = 0.0f;
}

// ---------------- CSR build + attr permutation (once per launch) ----------------
__global__ void build_csr_kernel(const int* __restrict__ ei) {
    int e = blockIdx.x * blockDim.x + threadIdx.x;
    if (e >= N_EDGES) return;
    int src = ei[e];
    int dst = ei[N_EDGES + e];
    int slot = atomicAdd(&g_deg[dst], 1);
    if (slot < MAXDEG) {
        int d = dst * MAXDEG + slot;
        g_src[d] = src;
        g_slot[e] = d;
    } else {
        g_slot[e] = -1;
    }
}

// 8 threads per edge, one float4 each: coalesced read, 128B-granular scattered write
__global__ void __launch_bounds__(256) permute_attr_kernel(const float* __restrict__ attr) {
    int t = blockIdx.x * 256 + threadIdx.x;
    int e = t >> 3, q = t & 7;
    if (e >= N_EDGES) return;
    int d = g_slot[e];
    if (d >= 0)
        ((float4*)g_attr_p)[(size_t)d * 8 + q] = __ldg((const float4*)attr + (size_t)e * 8 + q);
}

// ---------------- edge aggregation: warp per node, We register-resident, f32x2 math -------
// agg[n] = sum over incoming edges of relu( x[src] + attr_row @ We + be )
__global__ void __launch_bounds__(128, 4) agg_kernel(
    const float* __restrict__ xext, int xsel,
    const float* __restrict__ We, const float* __restrict__ be)
{
    int warp = (blockIdx.x * 128 + threadIdx.x) >> 5;
    int lane = threadIdx.x & 31;
    // grid sized so warp < N_NODES always; all warps full

    const float* x = sel_x(xext, xsel);
    const u64* x2 = (const u64*)x;   // float2 rows viewed as u64

    u64 w[EDIM];                      // lane owns output pair (2*lane, 2*lane+1)
    const u64* We2 = (const u64*)We;
#pragma unroll
    for (int k = 0; k < EDIM; k++) w[k] = We2[k * 32 + lane];
    u64 bias = ((const u64*)be)[lane];

    int d = g_deg[warp];
    if (d > MAXDEG) d = MAXDEG;

    float accx = 0.0f, accy = 0.0f;
    const int* srcp = g_src + (size_t)warp * MAXDEG;

    for (int base = 0; base < d; base += 32) {
        int cnt = d - base;
        if (cnt > 32) cnt = 32;
        int sl = (lane < cnt) ? srcp[base + lane] : 0;

        int j = 0;
        for (; j + 2 <= cnt; j += 2) {
            const float4* A0 = (const float4*)(g_attr_p + ((size_t)warp * MAXDEG + base + j) * EDIM);
            const float4* A1 = A0 + 8;
            int s0 = __shfl_sync(0xffffffffu, sl, j);
            int s1 = __shfl_sync(0xffffffffu, sl, j + 1);
            u64 X0 = x2[(size_t)s0 * 32 + lane];
            u64 X1 = x2[(size_t)s1 * 32 + lane];
            u64 acc0 = bias, acc1 = bias;

            float4 a0 = __ldg(A0 + 0), a1 = __ldg(A1 + 0);
            float4 b0 = __ldg(A0 + 1), b1 = __ldg(A1 + 1);
            float4 c0 = __ldg(A0 + 2), c1 = __ldg(A1 + 2);
            mac4(acc0, a0, w);      mac4(acc1, a1, w);
            float4 d0 = __ldg(A0 + 3), d1 = __ldg(A1 + 3);
            mac4(acc0, b0, w + 4);  mac4(acc1, b1, w + 4);
            a0 = __ldg(A0 + 4); a1 = __ldg(A1 + 4);
            mac4(acc0, c0, w + 8);  mac4(acc1, c1, w + 8);
            b0 = __ldg(A0 + 5); b1 = __ldg(A1 + 5);
            mac4(acc0, d0, w + 12); mac4(acc1, d1, w + 12);
            c0 = __ldg(A0 + 6); c1 = __ldg(A1 + 6);
            mac4(acc0, a0, w + 16); mac4(acc1, a1, w + 16);
            d0 = __ldg(A0 + 7); d1 = __ldg(A1 + 7);
            mac4(acc0, b0, w + 20); mac4(acc1, b1, w + 20);
            mac4(acc0, c0, w + 24); mac4(acc1, c1, w + 24);
            mac4(acc0, d0, w + 28); mac4(acc1, d1, w + 28);

            acc0 = add2(acc0, X0);
            acc1 = add2(acc1, X1);
            float l0, h0, l1, h1;
            unpk(acc0, l0, h0); unpk(acc1, l1, h1);
            accx += fmaxf(l0, 0.0f) + fmaxf(l1, 0.0f);
            accy += fmaxf(h0, 0.0f) + fmaxf(h1, 0.0f);
        }
        if (j < cnt) {  // remainder edge
            const float4* A0 = (const float4*)(g_attr_p + ((size_t)warp * MAXDEG + base + j) * EDIM);
            int s0 = __shfl_sync(0xffffffffu, sl, j);
            u64 X0 = x2[(size_t)s0 * 32 + lane];
            u64 acc0 = bias;
            float4 a = __ldg(A0 + 0), b = __ldg(A0 + 1), c = __ldg(A0 + 2), e = __ldg(A0 + 3);
            mac4(acc0, a, w);      mac4(acc0, b, w + 4);
            float4 f = __ldg(A0 + 4), g = __ldg(A0 + 5);
            mac4(acc0, c, w + 8);  mac4(acc0, e, w + 12);
            float4 h = __ldg(A0 + 6), i = __ldg(A0 + 7);
            mac4(acc0, f, w + 16); mac4(acc0, g, w + 20);
            mac4(acc0, h, w + 24); mac4(acc0, i, w + 28);
            acc0 = add2(acc0, X0);
            float l0, h0; unpk(acc0, l0, h0);
            accx += fmaxf(l0, 0.0f);
            accy += fmaxf(h0, 0.0f);
        }
    }
    float2 o; o.x = accx; o.y = accy;
    ((float2*)g_agg)[(size_t)warp * 32 + lane] = o;
}

// ---------------- node MLP + fused BN partial stats: 128 rows / 128 threads ----------------
// XOR-swizzled row tile: conflict-free column broadcast without padding (fits 48KB static)
#define SH(r, c) ((r) * 64 + ((c) ^ ((r) & 31)))

__global__ void __launch_bounds__(128) mlp_kernel(
    const float* __restrict__ xext, int xsel,
    const float* __restrict__ W1, const float* __restrict__ b1,
    const float* __restrict__ W2, const float* __restrict__ b2, int layer)
{
    __shared__ float sh[128 * 64];        // 32768 B
    __shared__ ulonglong2 sW[64 * 16];    // 16384 B  (total 49152 = static limit)
    const float* x = sel_x(xext, xsel);
    int tid = threadIdx.x;
    int rowbase = blockIdx.x * 128;

    // stage h = x + agg (coalesced global, swizzled smem)
    for (int i = tid; i < 128 * 64; i += 128) {
        int r = i >> 6, c = i & 63;
        float v = 0.0f;
        if (rowbase + r < N_NODES) {
            size_t g = (size_t)(rowbase + r) * HID + c;
            v = x[g] + g_agg[g];
        }
        sh[SH(r, c)] = v;
    }
    for (int i = tid; i < 1024; i += 128) sW[i] = ((const ulonglong2*)W1)[i];
    __syncthreads();

    u64 acc[32];
#pragma unroll
    for (int j = 0; j < 32; j++) acc[j] = ((const u64*)b1)[j];
    for (int k = 0; k < 64; k++) {
        u64 hk = pk(sh[SH(tid, k)]);
#pragma unroll
        for (int j = 0; j < 16; j++) {
            ulonglong2 wv = sW[k * 16 + j];
            fma2(acc[2 * j], hk, wv.x);
            fma2(acc[2 * j + 1], hk, wv.y);
        }
    }
    __syncthreads();
    // relu -> own row (thread-private row, no sync needed for sh)
#pragma unroll
    for (int j = 0; j < 32; j++) {
        float lo, hi; unpk(acc[j], lo, hi);
        sh[SH(tid, 2 * j)]     = fmaxf(lo, 0.0f);
        sh[SH(tid, 2 * j + 1)] = fmaxf(hi, 0.0f);
    }
    for (int i = tid; i < 1024; i += 128) sW[i] = ((const ulonglong2*)W2)[i];
    __syncthreads();

#pragma unroll
    for (int j = 0; j < 32; j++) acc[j] = ((const u64*)b2)[j];
    for (int k = 0; k < 64; k++) {
        u64 hk = pk(sh[SH(tid, k)]);
#pragma unroll
        for (int j = 0; j < 16; j++) {
            ulonglong2 wv = sW[k * 16 + j];
            fma2(acc[2 * j], hk, wv.x);
            fma2(acc[2 * j + 1], hk, wv.y);
        }
    }
    // write final (pre-BN) values to own row
#pragma unroll
    for (int j = 0; j < 32; j++) {
        float lo, hi; unpk(acc[j], lo, hi);
        sh[SH(tid, 2 * j)]     = lo;
        sh[SH(tid, 2 * j + 1)] = hi;
    }
    __syncthreads();   // all rows final; also: all sW reads done (red aliases sW below)

    // store to g_tmp (coalesced)
    for (int i = tid; i < 128 * 64; i += 128) {
        int r = i >> 6, c = i & 63;
        if (rowbase + r < N_NODES)
            g_tmp[(size_t)(rowbase + r) * HID + c] = sh[SH(r, c)];
    }

    // fused BN partial stats: per-feature sum / sumsq over this block's valid rows
    {
        float* red = (float*)sW;    // sW no longer needed
        int f = tid & 63, half = tid >> 6;
        float s = 0.0f, s2 = 0.0f;
        int rend = half * 64 + 64;
        for (int r = half * 64; r < rend; r++) {
            if (rowbase + r < N_NODES) {
                float v = sh[SH(r, f)];
                s += v; s2 += v * v;
            }
        }
        red[tid] = s;
        red[128 + tid] = s2;
        __syncthreads();
        if (tid < 64) {
            atomicAdd(&g_stats[layer * 128 + f],      red[tid] + red[tid + 64]);
            atomicAdd(&g_stats[layer * 128 + 64 + f], red[128 + tid] + red[192 + tid]);
        }
    }
}

// ---------------- BN apply + relu -> next layer's x buffer ---------------------------------
__global__ void __launch_bounds__(256) bn_kernel(
    int layer, const float* __restrict__ gamma, const float* __restrict__ beta, int outsel)
{
    size_t idx = (size_t)blockIdx.x * 256 + threadIdx.x;
    if (idx >= (size_t)N_NODES * HID) return;
    int f = (int)(idx & 63);
    const float inv = 1.0f / (float)N_NODES;
    float mean = g_stats[layer * 128 + f] * inv;
    float var  = g_stats[layer * 128 + 64 + f] * inv - mean * mean;
    float v = (g_tmp[idx] - mean) * rsqrtf(var + BN_EPS) * __ldg(gamma + f) + __ldg(beta + f);
    float* o = (outsel == 1) ? g_bufA : g_bufB;
    o[idx] = fmaxf(v, 0.0f);
}

// ---------------- output head: out = x3 @ Wout + bout --------------------------------------
__global__ void __launch_bounds__(64) out_kernel(
    const float* __restrict__ xext, int xsel,
    const float* __restrict__ Wout, const float* __restrict__ bout,
    float* __restrict__ out)
{
    __shared__ float sh[64 * 65];
    __shared__ float4 sW[64 * 16];
    const float* x = sel_x(xext, xsel);
    int tid = threadIdx.x;
    int rowbase = blockIdx.x * 64;

    for (int i = tid; i < 64 * 64; i += 64) {
        int r = i >> 6, c = i & 63;
        float v = 0.0f;
        if (rowbase + r < N_NODES) v = x[(size_t)(rowbase + r) * HID + c];
        sh[r * 65 + c] = v;
    }
    for (int i = tid; i < 1024; i += 64) sW[i] = ((const float4*)Wout)[i];
    __syncthreads();

    float4 acc[16];
#pragma unroll
    for (int j = 0; j < 16; j++) acc[j] = __ldg((const float4*)bout + j);
    for (int k = 0; k < 64; k++) {
        float hk = sh[tid * 65 + k];
#pragma unroll
        for (int j = 0; j < 16; j++) {
            float4 wv = sW[k * 16 + j];
            acc[j].x += hk * wv.x; acc[j].y += hk * wv.y;
            acc[j].z += hk * wv.z; acc[j].w += hk * wv.w;
        }
    }
    __syncthreads();
#pragma unroll
    for (int j = 0; j < 16; j++) {
        sh[tid * 65 + 4 * j + 0] = acc[j].x;
        sh[tid * 65 + 4 * j + 1] = acc[j].y;
        sh[tid * 65 + 4 * j + 2] = acc[j].z;
        sh[tid * 65 + 4 * j + 3] = acc[j].w;
    }
    __syncthreads();
    for (int i = tid; i < 64 * 64; i += 64) {
        int r = i >> 6, c = i & 63;
        if (rowbase + r < N_NODES)
            out[(size_t)(rowbase + r) * HID + c] = sh[r * 65 + c];
    }
}

// ---------------- launch --------------------------------------------------------------------
extern "C" void kernel_launch(void* const* d_in, const int* in_sizes, int n_in,
                              void* d_out, int out_size) {
    const float* x     = (const float*)d_in[0];
    const int*   ei    = (const int*)  d_in[1];
    const float* ea    = (const float*)d_in[2];
    const float* We    = (const float*)d_in[3];
    const float* be    = (const float*)d_in[4];
    const float* W1    = (const float*)d_in[5];
    const float* b1    = (const float*)d_in[6];
    const float* W2    = (const float*)d_in[7];
    const float* b2    = (const float*)d_in[8];
    const float* gamma = (const float*)d_in[9];
    const float* beta  = (const float*)d_in[10];
    const float* Wout  = (const float*)d_in[11];
    const float* bout  = (const float*)d_in[12];
    float* out = (float*)d_out;

    const int AGG_BLOCKS  = (N_NODES * 32 + 127) / 128;          // 25000
    const int MLP_BLOCKS  = (N_NODES + 127) / 128;               // 782
    const int OUT_BLOCKS  = (N_NODES + 63) / 64;                 // 1563
    const int BN_BLOCKS   = (int)(((size_t)N_NODES * HID + 255) / 256);
    const int PERM_BLOCKS = (N_EDGES * 8 + 255) / 256;           // 50000

    zero_kernel<<<(N_NODES + 255) / 256, 256>>>();
    build_csr_kernel<<<(N_EDGES + 255) / 256, 256>>>(ei);
    permute_attr_kernel<<<PERM_BLOCKS, 256>>>(ea);

    // layer 0: x = input, out -> bufA (sel 1)
    agg_kernel<<<AGG_BLOCKS, 128>>>(x, 0, We + 0 * EDIM * HID, be + 0 * HID);
    mlp_kernel<<<MLP_BLOCKS, 128>>>(x, 0, W1 + 0 * HID * HID, b1 + 0 * HID,
                                    W2 + 0 * HID * HID, b2 + 0 * HID, 0);
    bn_kernel<<<BN_BLOCKS, 256>>>(0, gamma + 0 * HID, beta + 0 * HID, 1);

    // layer 1: in bufA (sel 1), out -> bufB (sel 2)
    agg_kernel<<<AGG_BLOCKS, 128>>>(x, 1, We + 1 * EDIM * HID, be + 1 * HID);
    mlp_kernel<<<MLP_BLOCKS, 128>>>(x, 1, W1 + 1 * HID * HID, b1 + 1 * HID,
                                    W2 + 1 * HID * HID, b2 + 1 * HID, 1);
    bn_kernel<<<BN_BLOCKS, 256>>>(1, gamma + 1 * HID, beta + 1 * HID, 2);

    // layer 2: in bufB (sel 2), out -> bufA (sel 1)
    agg_kernel<<<AGG_BLOCKS, 128>>>(x, 2, We + 2 * EDIM * HID, be + 2 * HID);
    mlp_kernel<<<MLP_BLOCKS, 128>>>(x, 2, W1 + 2 * HID * HID, b1 + 2 * HID,
                                    W2 + 2 * HID * HID, b2 + 2 * HID, 2);
    bn_kernel<<<BN_BLOCKS, 256>>>(2, gamma + 2 * HID, beta + 2 * HID, 1);

    // output head: in bufA (sel 1)
    out_kernel<<<OUT_BLOCKS, 64>>>(x, 1, Wout, bout, out);
}

// round 6
// speedup vs baseline: 2.3347x; 1.3960x over previous
#include <cuda_runtime.h>

#define N_NODES 100000
#define N_EDGES 1600000
#define HID 64
#define EDIM 32
#define MAXDEG 64
#define N_LAYERS 3
#define BN_EPS 1e-5f

typedef unsigned long long u64;

// ---------------- scratch (static device globals; no allocation) ----------------
__device__ float g_agg[(size_t)N_NODES * HID];
__device__ float g_tmp[(size_t)N_NODES * HID];
__device__ float g_bufA[(size_t)N_NODES * HID];
__device__ float g_bufB[(size_t)N_NODES * HID];
__device__ float g_stats[N_LAYERS * 2 * HID];
__device__ int   g_deg[N_NODES];
__device__ int   g_src[(size_t)N_NODES * MAXDEG];
__device__ int   g_slot[N_EDGES];
__device__ float g_attr_p[(size_t)N_NODES * MAXDEG * EDIM];

__device__ __forceinline__ const float* sel_x(const float* xext, int sel) {
    return sel == 0 ? xext : (sel == 1 ? (const float*)g_bufA : (const float*)g_bufB);
}

// ---------------- packed f32x2 helpers ----------------
__device__ __forceinline__ u64 pk(float s) {
    u64 r; asm("mov.b64 %0, {%1, %1};" : "=l"(r) : "f"(s)); return r;
}
__device__ __forceinline__ void fma2(u64& d, u64 a, u64 b) {
    asm("fma.rn.f32x2 %0, %1, %2, %0;" : "+l"(d) : "l"(a), "l"(b));
}
__device__ __forceinline__ u64 add2(u64 a, u64 b) {
    u64 d; asm("add.rn.f32x2 %0, %1, %2;" : "=l"(d) : "l"(a), "l"(b)); return d;
}
__device__ __forceinline__ void unpk(u64 v, float& lo, float& hi) {
    asm("mov.b64 {%0, %1}, %2;" : "=f"(lo), "=f"(hi) : "l"(v));
}
__device__ __forceinline__ void mac4(u64& acc, float4 a, const u64* wp) {
    fma2(acc, pk(a.x), wp[0]); fma2(acc, pk(a.y), wp[1]);
    fma2(acc, pk(a.z), wp[2]); fma2(acc, pk(a.w), wp[3]);
}

// ---------------- init ----------------
__global__ void zero_kernel() {
    int i = blockIdx.x * blockDim.x + threadIdx.x;
    if (i < N_NODES) g_deg[i] = 0;
    if (i < N_LAYERS * 2 * HID) g_stats[i] = 0.0f;
}

// ---------------- CSR build + attr permutation (once per launch) ----------------
__global__ void build_csr_kernel(const int* __restrict__ ei) {
    int e = blockIdx.x * blockDim.x + threadIdx.x;
    if (e >= N_EDGES) return;
    int src = ei[e];
    int dst = ei[N_EDGES + e];
    int slot = atomicAdd(&g_deg[dst], 1);
    if (slot < MAXDEG) {
        int d = dst * MAXDEG + slot;
        g_src[d] = src;
        g_slot[e] = d;
    } else {
        g_slot[e] = -1;
    }
}

__global__ void __launch_bounds__(256) permute_attr_kernel(const float* __restrict__ attr) {
    int t = blockIdx.x * 256 + threadIdx.x;
    int e = t >> 3, q = t & 7;
    if (e >= N_EDGES) return;
    int d = g_slot[e];
    if (d >= 0)
        ((float4*)g_attr_p)[(size_t)d * 8 + q] = __ldg((const float4*)attr + (size_t)e * 8 + q);
}

// ---------------- edge aggregation: warp/node, We register-resident, 4-edge pipeline -------
__global__ void __launch_bounds__(128, 4) agg_kernel(
    const float* __restrict__ xext, int xsel,
    const float* __restrict__ We, const float* __restrict__ be)
{
    int warp = (blockIdx.x * 128 + threadIdx.x) >> 5;
    int lane = threadIdx.x & 31;

    const float* x = sel_x(xext, xsel);
    const u64* x2 = (const u64*)x;

    u64 w[EDIM];
    const u64* We2 = (const u64*)We;
#pragma unroll
    for (int k = 0; k < EDIM; k++) w[k] = We2[k * 32 + lane];
    u64 bias = ((const u64*)be)[lane];

    int d = g_deg[warp];
    if (d > MAXDEG) d = MAXDEG;

    float accx = 0.0f, accy = 0.0f;
    const int* srcp = g_src + (size_t)warp * MAXDEG;
    const float4* Abase = (const float4*)(g_attr_p + (size_t)warp * MAXDEG * EDIM);

    for (int base = 0; base < d; base += 32) {
        int cnt = d - base;
        if (cnt > 32) cnt = 32;
        int sl = (lane < cnt) ? srcp[base + lane] : 0;

        int j = 0;
        for (; j + 4 <= cnt; j += 4) {
            const float4* A0 = Abase + (size_t)(base + j) * 8;
            const float4* A1 = A0 + 8;
            const float4* A2 = A0 + 16;
            const float4* A3 = A0 + 24;
            int s0 = __shfl_sync(0xffffffffu, sl, j);
            int s1 = __shfl_sync(0xffffffffu, sl, j + 1);
            int s2 = __shfl_sync(0xffffffffu, sl, j + 2);
            int s3 = __shfl_sync(0xffffffffu, sl, j + 3);
            // all 4 gathers in flight immediately (L2-resident x)
            u64 X0 = x2[(size_t)s0 * 32 + lane];
            u64 X1 = x2[(size_t)s1 * 32 + lane];
            u64 X2 = x2[(size_t)s2 * 32 + lane];
            u64 X3 = x2[(size_t)s3 * 32 + lane];
            u64 a0 = bias, a1 = bias, a2 = bias, a3 = bias;
            // double-buffered attr chunks: next 4 loads issue over current 16 fma2s
            float4 p0 = __ldg(A0), p1 = __ldg(A1), p2 = __ldg(A2), p3 = __ldg(A3);
#pragma unroll
            for (int q = 0; q < 8; q++) {
                float4 n0, n1, n2, n3;
                if (q < 7) {
                    n0 = __ldg(A0 + q + 1); n1 = __ldg(A1 + q + 1);
                    n2 = __ldg(A2 + q + 1); n3 = __ldg(A3 + q + 1);
                }
                mac4(a0, p0, w + 4 * q); mac4(a1, p1, w + 4 * q);
                mac4(a2, p2, w + 4 * q); mac4(a3, p3, w + 4 * q);
                if (q < 7) { p0 = n0; p1 = n1; p2 = n2; p3 = n3; }
            }
            a0 = add2(a0, X0); a1 = add2(a1, X1);
            a2 = add2(a2, X2); a3 = add2(a3, X3);
            float l, h;
            unpk(a0, l, h); accx += fmaxf(l, 0.0f); accy += fmaxf(h, 0.0f);
            unpk(a1, l, h); accx += fmaxf(l, 0.0f); accy += fmaxf(h, 0.0f);
            unpk(a2, l, h); accx += fmaxf(l, 0.0f); accy += fmaxf(h, 0.0f);
            unpk(a3, l, h); accx += fmaxf(l, 0.0f); accy += fmaxf(h, 0.0f);
        }
        for (; j < cnt; j++) {   // remainder (<=3 edges)
            const float4* A0 = Abase + (size_t)(base + j) * 8;
            int s0 = __shfl_sync(0xffffffffu, sl, j);
            u64 X0 = x2[(size_t)s0 * 32 + lane];
            u64 a0 = bias;
            float4 p = __ldg(A0);
#pragma unroll
            for (int q = 0; q < 8; q++) {
                float4 n;
                if (q < 7) n = __ldg(A0 + q + 1);
                mac4(a0, p, w + 4 * q);
                if (q < 7) p = n;
            }
            a0 = add2(a0, X0);
            float l, h; unpk(a0, l, h);
            accx += fmaxf(l, 0.0f); accy += fmaxf(h, 0.0f);
        }
    }
    float2 o; o.x = accx; o.y = accy;
    ((float2*)g_agg)[(size_t)warp * 32 + lane] = o;
}

// ---------------- node MLP + fused BN partial stats: 128 rows / 128 threads ----------------
#define SH(r, c) ((r) * 64 + ((c) ^ ((r) & 31)))

__global__ void __launch_bounds__(128) mlp_kernel(
    const float* __restrict__ xext, int xsel,
    const float* __restrict__ W1, const float* __restrict__ b1,
    const float* __restrict__ W2, const float* __restrict__ b2, int layer)
{
    __shared__ float sh[128 * 64];
    __shared__ ulonglong2 sW[64 * 16];
    const float* x = sel_x(xext, xsel);
    int tid = threadIdx.x;
    int rowbase = blockIdx.x * 128;

    for (int i = tid; i < 128 * 64; i += 128) {
        int r = i >> 6, c = i & 63;
        float v = 0.0f;
        if (rowbase + r < N_NODES) {
            size_t g = (size_t)(rowbase + r) * HID + c;
            v = x[g] + g_agg[g];
        }
        sh[SH(r, c)] = v;
    }
    for (int i = tid; i < 1024; i += 128) sW[i] = ((const ulonglong2*)W1)[i];
    __syncthreads();

    u64 acc[32];
#pragma unroll
    for (int j = 0; j < 32; j++) acc[j] = ((const u64*)b1)[j];
    for (int k = 0; k < 64; k++) {
        u64 hk = pk(sh[SH(tid, k)]);
#pragma unroll
        for (int j = 0; j < 16; j++) {
            ulonglong2 wv = sW[k * 16 + j];
            fma2(acc[2 * j], hk, wv.x);
            fma2(acc[2 * j + 1], hk, wv.y);
        }
    }
    __syncthreads();
#pragma unroll
    for (int j = 0; j < 32; j++) {
        float lo, hi; unpk(acc[j], lo, hi);
        sh[SH(tid, 2 * j)]     = fmaxf(lo, 0.0f);
        sh[SH(tid, 2 * j + 1)] = fmaxf(hi, 0.0f);
    }
    for (int i = tid; i < 1024; i += 128) sW[i] = ((const ulonglong2*)W2)[i];
    __syncthreads();

#pragma unroll
    for (int j = 0; j < 32; j++) acc[j] = ((const u64*)b2)[j];
    for (int k = 0; k < 64; k++) {
        u64 hk = pk(sh[SH(tid, k)]);
#pragma unroll
        for (int j = 0; j < 16; j++) {
            ulonglong2 wv = sW[k * 16 + j];
            fma2(acc[2 * j], hk, wv.x);
            fma2(acc[2 * j + 1], hk, wv.y);
        }
    }
#pragma unroll
    for (int j = 0; j < 32; j++) {
        float lo, hi; unpk(acc[j], lo, hi);
        sh[SH(tid, 2 * j)]     = lo;
        sh[SH(tid, 2 * j + 1)] = hi;
    }
    __syncthreads();

    for (int i = tid; i < 128 * 64; i += 128) {
        int r = i >> 6, c = i & 63;
        if (rowbase + r < N_NODES)
            g_tmp[(size_t)(rowbase + r) * HID + c] = sh[SH(r, c)];
    }

    {
        float* red = (float*)sW;
        int f = tid & 63, half = tid >> 6;
        float s = 0.0f, s2 = 0.0f;
        int rend = half * 64 + 64;
        for (int r = half * 64; r < rend; r++) {
            if (rowbase + r < N_NODES) {
                float v = sh[SH(r, f)];
                s += v; s2 += v * v;
            }
        }
        red[tid] = s;
        red[128 + tid] = s2;
        __syncthreads();
        if (tid < 64) {
            atomicAdd(&g_stats[layer * 128 + f],      red[tid] + red[tid + 64]);
            atomicAdd(&g_stats[layer * 128 + 64 + f], red[128 + tid] + red[192 + tid]);
        }
    }
}

// ---------------- BN apply + relu -> next layer's x buffer ---------------------------------
__global__ void __launch_bounds__(256) bn_kernel(
    int layer, const float* __restrict__ gamma, const float* __restrict__ beta, int outsel)
{
    size_t idx = (size_t)blockIdx.x * 256 + threadIdx.x;
    if (idx >= (size_t)N_NODES * HID) return;
    int f = (int)(idx & 63);
    const float inv = 1.0f / (float)N_NODES;
    float mean = g_stats[layer * 128 + f] * inv;
    float var  = g_stats[layer * 128 + 64 + f] * inv - mean * mean;
    float v = (g_tmp[idx] - mean) * rsqrtf(var + BN_EPS) * __ldg(gamma + f) + __ldg(beta + f);
    float* o = (outsel == 1) ? g_bufA : g_bufB;
    o[idx] = fmaxf(v, 0.0f);
}

// ---------------- output head: out = x3 @ Wout + bout (128 rows / 128 threads) -------------
__global__ void __launch_bounds__(128) out_kernel(
    const float* __restrict__ xext, int xsel,
    const float* __restrict__ Wout, const float* __restrict__ bout,
    float* __restrict__ out)
{
    __shared__ float sh[128 * 64];
    __shared__ ulonglong2 sW[64 * 16];
    const float* x = sel_x(xext, xsel);
    int tid = threadIdx.x;
    int rowbase = blockIdx.x * 128;

    for (int i = tid; i < 128 * 64; i += 128) {
        int r = i >> 6, c = i & 63;
        float v = 0.0f;
        if (rowbase + r < N_NODES) v = x[(size_t)(rowbase + r) * HID + c];
        sh[SH(r, c)] = v;
    }
    for (int i = tid; i < 1024; i += 128) sW[i] = ((const ulonglong2*)Wout)[i];
    __syncthreads();

    u64 acc[32];
#pragma unroll
    for (int j = 0; j < 32; j++) acc[j] = ((const u64*)bout)[j];
    for (int k = 0; k < 64; k++) {
        u64 hk = pk(sh[SH(tid, k)]);
#pragma unroll
        for (int j = 0; j < 16; j++) {
            ulonglong2 wv = sW[k * 16 + j];
            fma2(acc[2 * j], hk, wv.x);
            fma2(acc[2 * j + 1], hk, wv.y);
        }
    }
    __syncthreads();
#pragma unroll
    for (int j = 0; j < 32; j++) {
        float lo, hi; unpk(acc[j], lo, hi);
        sh[SH(tid, 2 * j)]     = lo;
        sh[SH(tid, 2 * j + 1)] = hi;
    }
    __syncthreads();
    for (int i = tid; i < 128 * 64; i += 128) {
        int r = i >> 6, c = i & 63;
        if (rowbase + r < N_NODES)
            out[(size_t)(rowbase + r) * HID + c] = sh[SH(r, c)];
    }
}

// ---------------- launch --------------------------------------------------------------------
extern "C" void kernel_launch(void* const* d_in, const int* in_sizes, int n_in,
                              void* d_out, int out_size) {
    const float* x     = (const float*)d_in[0];
    const int*   ei    = (const int*)  d_in[1];
    const float* ea    = (const float*)d_in[2];
    const float* We    = (const float*)d_in[3];
    const float* be    = (const float*)d_in[4];
    const float* W1    = (const float*)d_in[5];
    const float* b1    = (const float*)d_in[6];
    const float* W2    = (const float*)d_in[7];
    const float* b2    = (const float*)d_in[8];
    const float* gamma = (const float*)d_in[9];
    const float* beta  = (const float*)d_in[10];
    const float* Wout  = (const float*)d_in[11];
    const float* bout  = (const float*)d_in[12];
    float* out = (float*)d_out;

    const int AGG_BLOCKS  = (N_NODES * 32 + 127) / 128;
    const int MLP_BLOCKS  = (N_NODES + 127) / 128;
    const int BN_BLOCKS   = (int)(((size_t)N_NODES * HID + 255) / 256);
    const int PERM_BLOCKS = (N_EDGES * 8 + 255) / 256;

    zero_kernel<<<(N_NODES + 255) / 256, 256>>>();
    build_csr_kernel<<<(N_EDGES + 255) / 256, 256>>>(ei);
    permute_attr_kernel<<<PERM_BLOCKS, 256>>>(ea);

    agg_kernel<<<AGG_BLOCKS, 128>>>(x, 0, We + 0 * EDIM * HID, be + 0 * HID);
    mlp_kernel<<<MLP_BLOCKS, 128>>>(x, 0, W1 + 0 * HID * HID, b1 + 0 * HID,
                                    W2 + 0 * HID * HID, b2 + 0 * HID, 0);
    bn_kernel<<<BN_BLOCKS, 256>>>(0, gamma + 0 * HID, beta + 0 * HID, 1);

    agg_kernel<<<AGG_BLOCKS, 128>>>(x, 1, We + 1 * EDIM * HID, be + 1 * HID);
    mlp_kernel<<<MLP_BLOCKS, 128>>>(x, 1, W1 + 1 * HID * HID, b1 + 1 * HID,
                                    W2 + 1 * HID * HID, b2 + 1 * HID, 1);
    bn_kernel<<<BN_BLOCKS, 256>>>(1, gamma + 1 * HID, beta + 1 * HID, 2);

    agg_kernel<<<AGG_BLOCKS, 128>>>(x, 2, We + 2 * EDIM * HID, be + 2 * HID);
    mlp_kernel<<<MLP_BLOCKS, 128>>>(x, 2, W1 + 2 * HID * HID, b1 + 2 * HID,
                                    W2 + 2 * HID * HID, b2 + 2 * HID, 2);
    bn_kernel<<<BN_BLOCKS, 256>>>(2, gamma + 2 * HID, beta + 2 * HID, 1);

    out_kernel<<<MLP_BLOCKS, 128>>>(x, 1, Wout, bout, out);
}